// round 16
// baseline (speedup 1.0000x reference)
#include <cuda_runtime.h>

// VolGeoNet trilinear interpolation.
// Morton-sort points (bin by 2x2x2 cells). Gather kernel: 128 threads per
// point, split into two 64-thread halves that each gather 4 of the 8 corner
// rows (4 batched float4 loads/thread -> ~16 data regs, no spills) and
// combine via a small smem partial buffer. launch_bounds(512,3) -> 48
// warps/SM (75% occ) with full 8-rows-in-flight MLP per point.
// Pre-pass scan uses warp shuffles (3 barriers) instead of Hillis-Steele.
//
// x:            (B, 3) float32
// grid_value:   (65^3, 1) float32
// grid_feature: (65^3, 256) float32
// outputs (concatenated in d_out): out (B,1) then feat (B,256)

#define N_GRID 64
#define N1     65
#define W_FEAT 256
#define B_MAX  262144
#define NBINS  32768           // 32^3 bins of 2x2x2 cells, Morton ordered
#define PTS_PER_CTA 4          // 512 threads / 128 per point

__device__ int g_counts[NBINS];    // zero-initialized at module load
__device__ int g_offsets[NBINS];
__device__ int g_cursor[NBINS];
__device__ int g_perm[B_MAX];
__device__ unsigned short g_bins[B_MAX];

__device__ __forceinline__ unsigned spread3(unsigned v) {
    v &= 0x3FF;
    v = (v | (v << 16)) & 0x30000FF;
    v = (v | (v << 8))  & 0x300F00F;
    v = (v | (v << 4))  & 0x30C30C3;
    v = (v | (v << 2))  & 0x9249249;
    return v;
}

__device__ __forceinline__ int point_bin(const float* __restrict__ x, int p) {
    const float rx = (x[p * 3 + 0] + 1.0f) * 32.0f;
    const float ry = (x[p * 3 + 1] + 1.0f) * 32.0f;
    const float rz = (x[p * 3 + 2] + 1.0f) * 32.0f;
    int ix = min(max(__float2int_rd(rx), 0), N_GRID - 1);
    int iy = min(max(__float2int_rd(ry), 0), N_GRID - 1);
    int iz = min(max(__float2int_rd(rz), 0), N_GRID - 1);
    unsigned bx = (unsigned)(ix >> 1), by = (unsigned)(iy >> 1), bz = (unsigned)(iz >> 1);
    return (int)(spread3(bx) | (spread3(by) << 1) | (spread3(bz) << 2));
}

__global__ void zero_counts_kernel() {
    int i = blockIdx.x * blockDim.x + threadIdx.x;
    if (i < NBINS) g_counts[i] = 0;
}

__global__ void hist_kernel(const float* __restrict__ x, int B) {
    int p = blockIdx.x * blockDim.x + threadIdx.x;
    if (p >= B) return;
    int bin = point_bin(x, p);
    g_bins[p] = (unsigned short)bin;
    atomicAdd(&g_counts[bin], 1);
}

// Single-block exclusive scan over NBINS = 32768 = 1024 threads x 32 elems.
// Warp-shuffle based: 2 barriers instead of 20.
__global__ __launch_bounds__(1024)
void scan_kernel() {
    __shared__ int warp_sums[32];
    const int t    = threadIdx.x;
    const int lane = t & 31;
    const int wid  = t >> 5;
    const int base = t * 32;

    int local[32];
    int s = 0;
    #pragma unroll
    for (int i = 0; i < 32; i++) {
        local[i] = g_counts[base + i];
        s += local[i];
    }

    // Inclusive warp scan of per-thread sums.
    int v = s;
    #pragma unroll
    for (int off = 1; off < 32; off <<= 1) {
        int n = __shfl_up_sync(0xFFFFFFFFu, v, off);
        if (lane >= off) v += n;
    }
    if (lane == 31) warp_sums[wid] = v;
    __syncthreads();

    if (wid == 0) {
        int ws = warp_sums[lane];
        #pragma unroll
        for (int off = 1; off < 32; off <<= 1) {
            int n = __shfl_up_sync(0xFFFFFFFFu, ws, off);
            if (lane >= off) ws += n;
        }
        warp_sums[lane] = ws;
    }
    __syncthreads();

    int excl = v - s + (wid > 0 ? warp_sums[wid - 1] : 0);
    #pragma unroll
    for (int i = 0; i < 32; i++) {
        g_offsets[base + i] = excl;
        g_cursor[base + i]  = excl;
        excl += local[i];
    }
}

__global__ void scatter_kernel(int B) {
    int p = blockIdx.x * blockDim.x + threadIdx.x;
    if (p >= B) return;
    int bin = (int)g_bins[p];
    int pos = atomicAdd(&g_cursor[bin], 1);
    g_perm[pos] = p;
}

// Gather: 512 threads = 4 points x 128 threads. Each point's 128 threads are
// two 64-thread halves: half h gathers corners with ox=h (4 rows, batched).
// Halves combine through smem. ~40 regs -> 3 CTAs/SM, 75% occupancy.
__global__ __launch_bounds__(512, 3)
void trilerp_kernel(const float* __restrict__ x,
                    const float* __restrict__ gval,
                    const float* __restrict__ gfeat,
                    float* __restrict__ out_val,
                    float* __restrict__ out_feat,
                    int B)
{
    __shared__ float4 s_part[PTS_PER_CTA][64];
    __shared__ float  s_valpart[PTS_PER_CTA];

    const int tid    = threadIdx.x;
    const int pt     = tid >> 7;            // 0..3 point slot
    const int half   = (tid >> 6) & 1;      // 0: ox=0 corners, 1: ox=1 corners
    const int lane64 = tid & 63;

    const int spos  = blockIdx.x * PTS_PER_CTA + pt;
    const bool in_range = (spos < B);
    const int point = in_range ? g_perm[spos] : 0;

    const float rx = (__ldg(x + point * 3 + 0) + 1.0f) * 32.0f;
    const float ry = (__ldg(x + point * 3 + 1) + 1.0f) * 32.0f;
    const float rz = (__ldg(x + point * 3 + 2) + 1.0f) * 32.0f;

    const bool valid = in_range &
                       (rx >= 0.0f) & (rx <= 64.0f) &
                       (ry >= 0.0f) & (ry <= 64.0f) &
                       (rz >= 0.0f) & (rz <= 64.0f);

    float4 acc = make_float4(0.0f, 0.0f, 0.0f, 0.0f);
    float  accv = 0.0f;

    if (valid) {
        const int ix = min(max(__float2int_rd(rx), 0), N_GRID - 1);
        const int iy = min(max(__float2int_rd(ry), 0), N_GRID - 1);
        const int iz = min(max(__float2int_rd(rz), 0), N_GRID - 1);

        const float tx = rx - (float)ix;
        const float ty = ry - (float)iy;
        const float tz = rz - (float)iz;

        // This half handles ox = half.
        const float wx  = half ? tx : 1.0f - tx;
        const float wy0 = 1.0f - ty, wy1 = ty;
        const float wz0 = 1.0f - tz, wz1 = tz;

        float w[4];
        w[0] = wx * wy0 * wz0;   // (oy0, oz0)
        w[1] = wx * wy0 * wz1;   // (oy0, oz1)
        w[2] = wx * wy1 * wz0;   // (oy1, oz0)
        w[3] = wx * wy1 * wz1;   // (oy1, oz1)

        const int base = (ix * N1 + iy) * N1 + iz + half * (N1 * N1);
        const int off4[4] = { 0, 1, N1, N1 + 1 };

        // Batch the 4 row loads (16 data regs), then the FMAs.
        float4 v[4];
        #pragma unroll
        for (int j = 0; j < 4; j++) {
            v[j] = __ldg(reinterpret_cast<const float4*>(
                             gfeat + (size_t)(base + off4[j]) * W_FEAT) + lane64);
        }
        #pragma unroll
        for (int j = 0; j < 4; j++) {
            const float wc = w[j];
            acc.x = fmaf(wc, v[j].x, acc.x);
            acc.y = fmaf(wc, v[j].y, acc.y);
            acc.z = fmaf(wc, v[j].z, acc.z);
            acc.w = fmaf(wc, v[j].w, acc.w);
        }
        if (lane64 == 0) {
            #pragma unroll
            for (int j = 0; j < 4; j++) {
                accv = fmaf(w[j], __ldg(gval + base + off4[j]), accv);
            }
        }
    }

    // Upper half publishes its partial; lower half combines + stores.
    if (half == 1) {
        s_part[pt][lane64] = acc;
        if (lane64 == 0) s_valpart[pt] = accv;
    }
    __syncthreads();

    if (half == 0 && in_range) {
        const float4 o = s_part[pt][lane64];
        acc.x += o.x; acc.y += o.y; acc.z += o.z; acc.w += o.w;
        __stcs(reinterpret_cast<float4*>(out_feat + (size_t)point * W_FEAT) + lane64, acc);
        if (lane64 == 0) __stcs(out_val + point, accv + s_valpart[pt]);
    }
}

extern "C" void kernel_launch(void* const* d_in, const int* in_sizes, int n_in,
                              void* d_out, int out_size)
{
    const float* x     = (const float*)d_in[0];
    const float* gval  = (const float*)d_in[1];
    const float* gfeat = (const float*)d_in[2];

    const int B = in_sizes[0] / 3;

    float* out_val  = (float*)d_out;        // (B, 1)
    float* out_feat = (float*)d_out + B;    // (B, 256)

    // g_counts is zero on entry (zeroed at module load for the first call,
    // re-zeroed at the end of every call thereafter).
    hist_kernel<<<(B + 255) / 256, 256>>>(x, B);
    scan_kernel<<<1, 1024>>>();
    scatter_kernel<<<(B + 255) / 256, 256>>>(B);

    const int grid = (B + PTS_PER_CTA - 1) / PTS_PER_CTA;
    trilerp_kernel<<<grid, 512>>>(x, gval, gfeat, out_val, out_feat, B);

    // Re-zero for the next invocation (keeps every call identical).
    zero_counts_kernel<<<(NBINS + 255) / 256, 256>>>();
}